// round 3
// baseline (speedup 1.0000x reference)
#include <cuda_runtime.h>

// Problem constants (fixed by setup_inputs)
#define HWX   3136      // 56*56
#define WW    56
#define CTOT  256
#define NTOT  64        // NB*T

// Scratch for intermediate y (temporal conv output), 64*256*56*56 floats = 205.5 MB
__device__ float g_y[51380224];

// ---------------------------------------------------------------------------
// Stage 1: temporal depthwise conv along T (within groups of 8 frames).
// One thread per (n, c, hw); loads all 8 timesteps once -> min HBM traffic.
// Generic over the provided weight arrays (no hardcoded shift patterns).
// ---------------------------------------------------------------------------
__global__ void temporal_kernel(
    const float* __restrict__ x,
    const float* __restrict__ w11, const float* __restrict__ w13,
    const float* __restrict__ w15, const float* __restrict__ w17,
    const float* __restrict__ w21, const float* __restrict__ w23,
    const float* __restrict__ w25, const float* __restrict__ w27)
{
    int idx = blockIdx.x * blockDim.x + threadIdx.x;
    const int total = 8 * CTOT * HWX;   // n(8) * c(256) * hw(3136)
    if (idx >= total) return;

    int hw   = idx % HWX;
    int rest = idx / HWX;
    int c    = rest % CTOT;
    int n    = rest / CTOT;

    const int stride_t = CTOT * HWX;
    const float* xb = x + ((size_t)n * 8 * CTOT + c) * HWX + hw;

    float v[8];
#pragma unroll
    for (int t = 0; t < 8; t++) v[t] = xb[(size_t)t * stride_t];

    // channel -> (kernel size, weight array, channel-in-group)
    int k, cg; const float* wp;
    if      (c < 16)  { k = 1; wp = w11; cg = c;       }
    else if (c < 32)  { k = 3; wp = w13; cg = c - 16;  }
    else if (c < 48)  { k = 5; wp = w15; cg = c - 32;  }
    else if (c < 64)  { k = 7; wp = w17; cg = c - 48;  }
    else if (c < 112) { k = 1; wp = w21; cg = c - 64;  }
    else if (c < 160) { k = 3; wp = w23; cg = c - 112; }
    else if (c < 208) { k = 5; wp = w25; cg = c - 160; }
    else              { k = 7; wp = w27; cg = c - 208; }

    float wr[7];
#pragma unroll
    for (int j = 0; j < 7; j++)
        wr[j] = (j < k) ? __ldg(&wp[cg * k + j]) : 0.0f;
    int pad = (k - 1) >> 1;

    float* yb = g_y + ((size_t)n * 8 * CTOT + c) * HWX + hw;
#pragma unroll
    for (int t = 0; t < 8; t++) {
        float s = 0.0f;
#pragma unroll
        for (int j = 0; j < 7; j++) {
            int tt = t + j - pad;
            if (j < k && tt >= 0 && tt < 8) s += wr[j] * v[tt];
        }
        yb[(size_t)t * stride_t] = s;
    }
}

// ---------------------------------------------------------------------------
// Stage 2: grouped 3x3 conv (pad 1), cross-correlation semantics.
//   oc in [0,64)   : in-channels [0,64)   with w2d1 [64][64][3][3]
//   oc in [64,256) : in-channels [64,256) with w2d2 [192][192][3][3]
// Block (56,4): tile = 16 out-channels x 8 rows x 56 cols of one image.
// Per ic: stage 10x58 halo tile + 16x9 weights in smem; each thread holds
// two 3x3 input windows in registers and does 2*16*9 = 288 FMA.
// ---------------------------------------------------------------------------
__global__ __launch_bounds__(224) void conv3x3_kernel(
    const float* __restrict__ w2d1,
    const float* __restrict__ w2d2,
    float* __restrict__ out)
{
    __shared__ float s_in[10][60];  // 10 rows x 58 cols (padded to 60)
    __shared__ float s_w[16][9];

    const int tx  = threadIdx.x;          // 0..55  (w position)
    const int ty  = threadIdx.y;          // 0..3
    const int tid = ty * 56 + tx;

    const int img = blockIdx.z;           // 0..63
    const int oct = blockIdx.y;           // 0..15 -> 16 oc each
    const int h0  = blockIdx.x * 8;       // 0,8,...,48
    const int oc0 = oct * 16;

    const bool groupA  = (oc0 < 64);
    const int  ic_base = groupA ? 0  : 64;
    const int  ic_n    = groupA ? 64 : 192;
    const float* wsrc  = groupA ? (w2d1 + (size_t)oc0 * 64 * 9)
                                : (w2d2 + (size_t)(oc0 - 64) * 192 * 9);

    float acc0[16], acc1[16];
#pragma unroll
    for (int i = 0; i < 16; i++) { acc0[i] = 0.0f; acc1[i] = 0.0f; }

    const float* ybase = g_y + (size_t)img * CTOT * HWX + (size_t)ic_base * HWX;

    for (int ici = 0; ici < ic_n; ici++) {
        const float* yp = ybase + (size_t)ici * HWX;

        // Stage the 10x58 input halo tile (zero-padded at borders)
        for (int i = tid; i < 580; i += 224) {
            int r  = i / 58;
            int cc = i - r * 58;
            int gh = h0 - 1 + r;
            int gw = cc - 1;
            float vv = 0.0f;
            if ((unsigned)gh < 56u && (unsigned)gw < 56u)
                vv = yp[gh * WW + gw];
            s_in[r][cc] = vv;
        }
        // Stage the 16x9 weights for this ic
        if (tid < 144) {
            int oci = tid / 9, t9 = tid - oci * 9;
            s_w[oci][t9] = wsrc[((size_t)oci * ic_n + ici) * 9 + t9];
        }
        __syncthreads();

        // Two 3x3 windows (rows ty and ty+4 of the tile)
        float i0[9], i1[9];
#pragma unroll
        for (int dy = 0; dy < 3; dy++)
#pragma unroll
            for (int dx = 0; dx < 3; dx++) {
                i0[dy * 3 + dx] = s_in[ty + dy][tx + dx];
                i1[dy * 3 + dx] = s_in[ty + 4 + dy][tx + dx];
            }

#pragma unroll
        for (int oci = 0; oci < 16; oci++) {
#pragma unroll
            for (int t9 = 0; t9 < 9; t9++) {
                float wv = s_w[oci][t9];
                acc0[oci] += wv * i0[t9];
                acc1[oci] += wv * i1[t9];
            }
        }
        __syncthreads();
    }

    // Write back: coalesced along tx
    const size_t obase = (size_t)img * CTOT * HWX + (size_t)oc0 * HWX;
#pragma unroll
    for (int oci = 0; oci < 16; oci++) {
        out[obase + (size_t)oci * HWX + (h0 + ty)     * WW + tx] = acc0[oci];
        out[obase + (size_t)oci * HWX + (h0 + ty + 4) * WW + tx] = acc1[oci];
    }
}

// ---------------------------------------------------------------------------
// Inputs (metadata order): x, w11, w13, w15, w17, w21, w23, w25, w27,
//                          w2d1, w2d2, n_segment
// ---------------------------------------------------------------------------
extern "C" void kernel_launch(void* const* d_in, const int* in_sizes, int n_in,
                              void* d_out, int out_size)
{
    const float* x    = (const float*)d_in[0];
    const float* w11  = (const float*)d_in[1];
    const float* w13  = (const float*)d_in[2];
    const float* w15  = (const float*)d_in[3];
    const float* w17  = (const float*)d_in[4];
    const float* w21  = (const float*)d_in[5];
    const float* w23  = (const float*)d_in[6];
    const float* w25  = (const float*)d_in[7];
    const float* w27  = (const float*)d_in[8];
    const float* w2d1 = (const float*)d_in[9];
    const float* w2d2 = (const float*)d_in[10];
    float* out = (float*)d_out;

    const int total = 8 * CTOT * HWX;
    temporal_kernel<<<(total + 255) / 256, 256>>>(
        x, w11, w13, w15, w17, w21, w23, w25, w27);

    dim3 grid(7, 16, NTOT);   // h-tiles, oc-tiles, images
    dim3 block(56, 4);
    conv3x3_kernel<<<grid, block>>>(w2d1, w2d2, out);
}

// round 5
// speedup vs baseline: 1.0090x; 1.0090x over previous
#include <cuda_runtime.h>

// Problem constants (fixed by setup_inputs)
#define HWX   3136      // 56*56
#define WW    56
#define CTOT  256
#define NTOT  64        // NB*T

// Scratch for intermediate y (temporal conv output), 64*256*56*56 floats = 205.5 MB
__device__ float g_y[51380224];

// ---------------------------------------------------------------------------
// Stage 1: temporal depthwise conv along T (within groups of 8 frames).
// One thread per (n, c, hw); loads all 8 timesteps once -> min HBM traffic.
// Generic over the provided weight arrays (no hardcoded shift patterns).
// ---------------------------------------------------------------------------
__global__ void temporal_kernel(
    const float* __restrict__ x,
    const float* __restrict__ w11, const float* __restrict__ w13,
    const float* __restrict__ w15, const float* __restrict__ w17,
    const float* __restrict__ w21, const float* __restrict__ w23,
    const float* __restrict__ w25, const float* __restrict__ w27)
{
    int idx = blockIdx.x * blockDim.x + threadIdx.x;
    const int total = 8 * CTOT * HWX;   // n(8) * c(256) * hw(3136)
    if (idx >= total) return;

    int hw   = idx % HWX;
    int rest = idx / HWX;
    int c    = rest % CTOT;
    int n    = rest / CTOT;

    const int stride_t = CTOT * HWX;
    const float* xb = x + ((size_t)n * 8 * CTOT + c) * HWX + hw;

    float v[8];
#pragma unroll
    for (int t = 0; t < 8; t++) v[t] = xb[(size_t)t * stride_t];

    // channel -> (kernel size, weight array, channel-in-group)
    int k, cg; const float* wp;
    if      (c < 16)  { k = 1; wp = w11; cg = c;       }
    else if (c < 32)  { k = 3; wp = w13; cg = c - 16;  }
    else if (c < 48)  { k = 5; wp = w15; cg = c - 32;  }
    else if (c < 64)  { k = 7; wp = w17; cg = c - 48;  }
    else if (c < 112) { k = 1; wp = w21; cg = c - 64;  }
    else if (c < 160) { k = 3; wp = w23; cg = c - 112; }
    else if (c < 208) { k = 5; wp = w25; cg = c - 160; }
    else              { k = 7; wp = w27; cg = c - 208; }

    float wr[7];
#pragma unroll
    for (int j = 0; j < 7; j++)
        wr[j] = (j < k) ? __ldg(&wp[cg * k + j]) : 0.0f;
    int pad = (k - 1) >> 1;

    float* yb = g_y + ((size_t)n * 8 * CTOT + c) * HWX + hw;
#pragma unroll
    for (int t = 0; t < 8; t++) {
        float s = 0.0f;
#pragma unroll
        for (int j = 0; j < 7; j++) {
            int tt = t + j - pad;
            if (j < k && tt >= 0 && tt < 8) s += wr[j] * v[tt];
        }
        yb[(size_t)t * stride_t] = s;
    }
}

// ---------------------------------------------------------------------------
// Stage 2: grouped 3x3 conv (pad 1), cross-correlation semantics.
//   oc in [0,64)   : in-channels [0,64)   with w2d1 [64][64][3][3]
//   oc in [64,256) : in-channels [64,256) with w2d2 [192][192][3][3]
// Block (56,4): tile = 16 out-channels x 8 rows x 56 cols of one image.
// Per ic: stage 10x58 halo tile + 16x9 weights in smem; each thread holds
// two 3x3 input windows in registers and does 2*16*9 = 288 FMA.
// ---------------------------------------------------------------------------
__global__ __launch_bounds__(224) void conv3x3_kernel(
    const float* __restrict__ w2d1,
    const float* __restrict__ w2d2,
    float* __restrict__ out)
{
    __shared__ float s_in[10][60];  // 10 rows x 58 cols (padded to 60)
    __shared__ float s_w[16][9];

    const int tx  = threadIdx.x;          // 0..55  (w position)
    const int ty  = threadIdx.y;          // 0..3
    const int tid = ty * 56 + tx;

    const int img = blockIdx.z;           // 0..63
    const int oct = blockIdx.y;           // 0..15 -> 16 oc each
    const int h0  = blockIdx.x * 8;       // 0,8,...,48
    const int oc0 = oct * 16;

    const bool groupA  = (oc0 < 64);
    const int  ic_base = groupA ? 0  : 64;
    const int  ic_n    = groupA ? 64 : 192;
    const float* wsrc  = groupA ? (w2d1 + (size_t)oc0 * 64 * 9)
                                : (w2d2 + (size_t)(oc0 - 64) * 192 * 9);

    float acc0[16], acc1[16];
#pragma unroll
    for (int i = 0; i < 16; i++) { acc0[i] = 0.0f; acc1[i] = 0.0f; }

    const float* ybase = g_y + (size_t)img * CTOT * HWX + (size_t)ic_base * HWX;

    for (int ici = 0; ici < ic_n; ici++) {
        const float* yp = ybase + (size_t)ici * HWX;

        // Stage the 10x58 input halo tile (zero-padded at borders)
        for (int i = tid; i < 580; i += 224) {
            int r  = i / 58;
            int cc = i - r * 58;
            int gh = h0 - 1 + r;
            int gw = cc - 1;
            float vv = 0.0f;
            if ((unsigned)gh < 56u && (unsigned)gw < 56u)
                vv = yp[gh * WW + gw];
            s_in[r][cc] = vv;
        }
        // Stage the 16x9 weights for this ic
        if (tid < 144) {
            int oci = tid / 9, t9 = tid - oci * 9;
            s_w[oci][t9] = wsrc[((size_t)oci * ic_n + ici) * 9 + t9];
        }
        __syncthreads();

        // Two 3x3 windows (rows ty and ty+4 of the tile)
        float i0[9], i1[9];
#pragma unroll
        for (int dy = 0; dy < 3; dy++)
#pragma unroll
            for (int dx = 0; dx < 3; dx++) {
                i0[dy * 3 + dx] = s_in[ty + dy][tx + dx];
                i1[dy * 3 + dx] = s_in[ty + 4 + dy][tx + dx];
            }

#pragma unroll
        for (int oci = 0; oci < 16; oci++) {
#pragma unroll
            for (int t9 = 0; t9 < 9; t9++) {
                float wv = s_w[oci][t9];
                acc0[oci] += wv * i0[t9];
                acc1[oci] += wv * i1[t9];
            }
        }
        __syncthreads();
    }

    // Write back: coalesced along tx
    const size_t obase = (size_t)img * CTOT * HWX + (size_t)oc0 * HWX;
#pragma unroll
    for (int oci = 0; oci < 16; oci++) {
        out[obase + (size_t)oci * HWX + (h0 + ty)     * WW + tx] = acc0[oci];
        out[obase + (size_t)oci * HWX + (h0 + ty + 4) * WW + tx] = acc1[oci];
    }
}

// ---------------------------------------------------------------------------
// Inputs (metadata order): x, w11, w13, w15, w17, w21, w23, w25, w27,
//                          w2d1, w2d2, n_segment
// ---------------------------------------------------------------------------
extern "C" void kernel_launch(void* const* d_in, const int* in_sizes, int n_in,
                              void* d_out, int out_size)
{
    const float* x    = (const float*)d_in[0];
    const float* w11  = (const float*)d_in[1];
    const float* w13  = (const float*)d_in[2];
    const float* w15  = (const float*)d_in[3];
    const float* w17  = (const float*)d_in[4];
    const float* w21  = (const float*)d_in[5];
    const float* w23  = (const float*)d_in[6];
    const float* w25  = (const float*)d_in[7];
    const float* w27  = (const float*)d_in[8];
    const float* w2d1 = (const float*)d_in[9];
    const float* w2d2 = (const float*)d_in[10];
    float* out = (float*)d_out;

    const int total = 8 * CTOT * HWX;
    temporal_kernel<<<(total + 255) / 256, 256>>>(
        x, w11, w13, w15, w17, w21, w23, w25, w27);

    dim3 grid(7, 16, NTOT);   // h-tiles, oc-tiles, images
    dim3 block(56, 4);
    conv3x3_kernel<<<grid, block>>>(w2d1, w2d2, out);
}

// round 7
// speedup vs baseline: 6.0036x; 5.9498x over previous
#include <cuda_runtime.h>
#include <cstdint>

#define HWX   3136
#define WW    56
#define CTOT  256
#define NIMG  64
#define NPIX  (NIMG * HWX)          // 200704 = 784 * 256

// Intermediate y, NHWC fp32 (tf32-rounded): [img*hw][256]
__device__ float g_y[(size_t)NPIX * CTOT];
// GEMM weights, tf32-rounded: gA[oc 64][tap*64+ic], gB[oc 192][tap*192+ic]
__device__ float g_wA[64 * 576];
__device__ float g_wB[192 * 1728];

__device__ __forceinline__ uint32_t smem_u32(const void* p) {
    uint32_t a;
    asm("{ .reg .u64 t; cvta.to.shared.u64 t, %1; cvt.u32.u64 %0, t; }" : "=r"(a) : "l"(p));
    return a;
}
__device__ __forceinline__ float tf32r(float v) {
    uint32_t u;
    asm("cvt.rna.tf32.f32 %0, %1;" : "=r"(u) : "f"(v));
    return __uint_as_float(u);
}

// ---------------------------------------------------------------------------
// Stage 1: temporal DW conv, NCHW -> NHWC (tf32-rounded), smem transpose.
// ---------------------------------------------------------------------------
__global__ __launch_bounds__(256) void temporal_nhwc_kernel(
    const float* __restrict__ x,
    const float* __restrict__ w11, const float* __restrict__ w13,
    const float* __restrict__ w15, const float* __restrict__ w17,
    const float* __restrict__ w21, const float* __restrict__ w23,
    const float* __restrict__ w25, const float* __restrict__ w27)
{
    __shared__ float s[32][33];
    const int tx = threadIdx.x, ty = threadIdx.y;
    const int n = blockIdx.z, c0 = blockIdx.y * 32, hw0 = blockIdx.x * 32;

    float v[4][8], o[4][8];
#pragma unroll
    for (int j = 0; j < 4; j++) {
        int c = c0 + ty * 4 + j;
        const float* xb = x + ((size_t)(n * 8) * CTOT + c) * HWX + hw0 + tx;
#pragma unroll
        for (int t = 0; t < 8; t++) v[j][t] = xb[(size_t)t * CTOT * HWX];
    }
#pragma unroll
    for (int j = 0; j < 4; j++) {
        int c = c0 + ty * 4 + j;
        int k, cg; const float* wp;
        if      (c < 16)  { k = 1; wp = w11; cg = c;       }
        else if (c < 32)  { k = 3; wp = w13; cg = c - 16;  }
        else if (c < 48)  { k = 5; wp = w15; cg = c - 32;  }
        else if (c < 64)  { k = 7; wp = w17; cg = c - 48;  }
        else if (c < 112) { k = 1; wp = w21; cg = c - 64;  }
        else if (c < 160) { k = 3; wp = w23; cg = c - 112; }
        else if (c < 208) { k = 5; wp = w25; cg = c - 160; }
        else              { k = 7; wp = w27; cg = c - 208; }
        float wr[7];
#pragma unroll
        for (int q = 0; q < 7; q++) wr[q] = (q < k) ? __ldg(&wp[cg * k + q]) : 0.0f;
        int pad = (k - 1) >> 1;
#pragma unroll
        for (int t = 0; t < 8; t++) {
            float sum = 0.0f;
#pragma unroll
            for (int q = 0; q < 7; q++) {
                int tt = t + q - pad;
                if (q < k && tt >= 0 && tt < 8) sum += wr[q] * v[j][tt];
            }
            o[j][t] = tf32r(sum);
        }
    }
#pragma unroll
    for (int t = 0; t < 8; t++) {
#pragma unroll
        for (int j = 0; j < 4; j++) s[tx][ty * 4 + j] = o[j][t];
        __syncthreads();
        float* yb = g_y + ((size_t)(n * 8 + t) * HWX + hw0) * CTOT + c0;
#pragma unroll
        for (int j = 0; j < 4; j++)
            yb[(size_t)(ty * 4 + j) * CTOT + tx] = s[ty * 4 + j][tx];
        __syncthreads();
    }
}

// ---------------------------------------------------------------------------
// Weight prep: [oc][ic][3][3] -> [oc][tap*icn + ic], tf32-rounded
// ---------------------------------------------------------------------------
__global__ void prep_w_kernel(const float* __restrict__ w2d1,
                              const float* __restrict__ w2d2)
{
    int i = blockIdx.x * 256 + threadIdx.x;     // < 368640
    if (i < 64 * 576) {
        int oc = i / 576, r = i % 576, tap = r / 64, ic = r % 64;
        g_wA[i] = tf32r(w2d1[(oc * 64 + ic) * 9 + tap]);
    } else {
        int j = i - 64 * 576;
        if (j < 192 * 1728) {
            int oc = j / 1728, r = j % 1728, tap = r / 192, ic = r % 192;
            g_wB[j] = tf32r(w2d2[(oc * 192 + ic) * 9 + tap]);
        }
    }
}

// ---------------------------------------------------------------------------
// Stage 2: implicit GEMM with mma.sync.m16n8k8 tf32.
// Grid (4 octiles fast, 784 pixel tiles). CTA: 64 oc x 256 px, 8 warps 32x64.
// smem: sA[2][64][36] floats, sB[2][256][40] floats. cp.async double buffer.
// ---------------------------------------------------------------------------
#define SA_F 2304               // 64*36 floats = 9216 B
#define SB_F 10240              // 256*40 floats = 40960 B
#define SMEM_BYTES (2 * (SA_F + SB_F) * 4)   // 100352

__global__ __launch_bounds__(256) void gemm_conv_kernel(float* __restrict__ out)
{
    extern __shared__ float smf[];
    const uint32_t smb = smem_u32(smf);
    const int tid = threadIdx.x, wid = tid >> 5, lane = tid & 31;
    const int octile = blockIdx.x;
    const int n0 = blockIdx.y * 256;

    const bool isA = (octile == 0);
    const int icn   = isA ? 64 : 192;
    const int Ktot  = isA ? 576 : 1728;
    const int nicb  = icn >> 5;           // 2 or 6
    const int nch   = Ktot >> 5;          // 18 or 54
    const int icbase = isA ? 0 : 64;
    const float* Wg = isA ? g_wA : (g_wB + (size_t)(octile - 1) * 64 * 1728);

    // Per-thread B staging coords (8 items, pixel r = (tid + 256*it) >> 3)
    int pn[8], ph_[8], pw_[8];
#pragma unroll
    for (int it = 0; it < 8; ++it) {
        int r = (tid + it * 256) >> 3;
        int nn = n0 + r;
        int hw = nn % HWX;
        pn[it] = nn; ph_[it] = hw / WW; pw_[it] = hw % WW;
    }
    const int q8 = tid & 7;

    auto stage = [&](int ch, int buf) {
        int tap = ch / nicb, icq = ch - tap * nicb;
        int dy = tap / 3 - 1, dx = tap - (tap / 3) * 3 - 1;
        // A tile: 64 oc x 32 k
        {
            const float* asrc = Wg + tap * icn + icq * 32;
#pragma unroll
            for (int it = 0; it < 2; ++it) {
                int i = tid + it * 256;
                int m = i >> 3, q = i & 7;
                uint32_t dst = smb + buf * (SA_F * 4) + m * 144 + q * 16;
                const float* src = asrc + (size_t)m * Ktot + q * 4;
                asm volatile("cp.async.cg.shared.global [%0], [%1], 16;"
                             :: "r"(dst), "l"(src));
            }
        }
        // B tile: 256 px x 32 ic (pixel-major, stride 40 floats)
        {
            int ic0 = icbase + icq * 32;
            int shift = dy * WW + dx;
#pragma unroll
            for (int it = 0; it < 8; ++it) {
                int r = (tid + it * 256) >> 3;
                bool inb = ((unsigned)(ph_[it] + dy) < 56u) &&
                           ((unsigned)(pw_[it] + dx) < 56u);
                const float* src = g_y + (size_t)(pn[it] + shift) * CTOT + ic0 + q8 * 4;
                if (!inb) src = g_y;
                uint32_t sz = inb ? 16u : 0u;
                uint32_t dst = smb + 2 * (SA_F * 4) + buf * (SB_F * 4) + r * 160 + q8 * 16;
                asm volatile("cp.async.cg.shared.global [%0], [%1], 16, %2;"
                             :: "r"(dst), "l"(src), "r"(sz));
            }
        }
        asm volatile("cp.async.commit_group;" ::: "memory");
    };

    float acc[2][8][4];
#pragma unroll
    for (int mt = 0; mt < 2; ++mt)
#pragma unroll
        for (int nt = 0; nt < 8; ++nt)
#pragma unroll
            for (int e = 0; e < 4; ++e) acc[mt][nt][e] = 0.0f;

    const int wm = wid & 1, wn = wid >> 1;
    const int g = lane >> 2, t = lane & 3;

    stage(0, 0);

    for (int ch = 0; ch < nch; ++ch) {
        if (ch + 1 < nch) {
            stage(ch + 1, (ch + 1) & 1);
            asm volatile("cp.async.wait_group 1;" ::: "memory");
        } else {
            asm volatile("cp.async.wait_group 0;" ::: "memory");
        }
        __syncthreads();

        const float* sA = smf + (ch & 1) * SA_F;
        const float* sB = smf + 2 * SA_F + (ch & 1) * SB_F;
        const float* sAr = sA + (wm * 32 + g) * 36;
        const float* sBr = sB + (wn * 64 + g) * 40;

#pragma unroll
        for (int ks = 0; ks < 4; ++ks) {
            int k0 = ks * 8 + t;
            uint32_t a[2][4], b[8][2];
#pragma unroll
            for (int mt = 0; mt < 2; ++mt) {
                const float* p = sAr + mt * 16 * 36;
                a[mt][0] = __float_as_uint(p[k0]);
                a[mt][1] = __float_as_uint(p[8 * 36 + k0]);
                a[mt][2] = __float_as_uint(p[k0 + 4]);
                a[mt][3] = __float_as_uint(p[8 * 36 + k0 + 4]);
            }
#pragma unroll
            for (int nt = 0; nt < 8; ++nt) {
                const float* p = sBr + nt * 8 * 40;
                b[nt][0] = __float_as_uint(p[k0]);
                b[nt][1] = __float_as_uint(p[k0 + 4]);
            }
#pragma unroll
            for (int mt = 0; mt < 2; ++mt)
#pragma unroll
                for (int nt = 0; nt < 8; ++nt)
                    asm volatile(
                        "mma.sync.aligned.m16n8k8.row.col.f32.tf32.tf32.f32 "
                        "{%0,%1,%2,%3}, {%4,%5,%6,%7}, {%8,%9}, {%0,%1,%2,%3};"
                        : "+f"(acc[mt][nt][0]), "+f"(acc[mt][nt][1]),
                          "+f"(acc[mt][nt][2]), "+f"(acc[mt][nt][3])
                        : "r"(a[mt][0]), "r"(a[mt][1]), "r"(a[mt][2]), "r"(a[mt][3]),
                          "r"(b[nt][0]), "r"(b[nt][1]));
        }
        __syncthreads();
    }

    // Epilogue: D[oc][pixel] -> out NCHW, float2 stores (even pixel pairs)
    const int oc_b = octile * 64 + wm * 32 + g;
#pragma unroll
    for (int mt = 0; mt < 2; ++mt) {
#pragma unroll
        for (int nt = 0; nt < 8; ++nt) {
            int nn  = n0 + wn * 64 + nt * 8 + 2 * t;
            int img = nn / HWX, hw = nn - img * HWX;
            size_t r0 = ((size_t)img * CTOT + (oc_b + mt * 16))     * HWX + hw;
            size_t r1 = ((size_t)img * CTOT + (oc_b + mt * 16 + 8)) * HWX + hw;
            *(float2*)(out + r0) = make_float2(acc[mt][nt][0], acc[mt][nt][1]);
            *(float2*)(out + r1) = make_float2(acc[mt][nt][2], acc[mt][nt][3]);
        }
    }
}

// ---------------------------------------------------------------------------
// Inputs: x, w11, w13, w15, w17, w21, w23, w25, w27, w2d1, w2d2, n_segment
// ---------------------------------------------------------------------------
extern "C" void kernel_launch(void* const* d_in, const int* in_sizes, int n_in,
                              void* d_out, int out_size)
{
    const float* x    = (const float*)d_in[0];
    const float* w11  = (const float*)d_in[1];
    const float* w13  = (const float*)d_in[2];
    const float* w15  = (const float*)d_in[3];
    const float* w17  = (const float*)d_in[4];
    const float* w21  = (const float*)d_in[5];
    const float* w23  = (const float*)d_in[6];
    const float* w25  = (const float*)d_in[7];
    const float* w27  = (const float*)d_in[8];
    const float* w2d1 = (const float*)d_in[9];
    const float* w2d2 = (const float*)d_in[10];
    float* out = (float*)d_out;

    cudaFuncSetAttribute(gemm_conv_kernel,
                         cudaFuncAttributeMaxDynamicSharedMemorySize, SMEM_BYTES);

    dim3 g1(98, 8, 8), b1(32, 8);
    temporal_nhwc_kernel<<<g1, b1>>>(x, w11, w13, w15, w17, w21, w23, w25, w27);
    prep_w_kernel<<<1440, 256>>>(w2d1, w2d2);
    gemm_conv_kernel<<<dim3(4, 784), 256, SMEM_BYTES>>>(out);
}

// round 8
// speedup vs baseline: 9.4306x; 1.5708x over previous
#include <cuda_runtime.h>
#include <cuda_fp16.h>
#include <cstdint>

#define HWX   3136
#define WW    56
#define CTOT  256
#define NIMG  64
#define NPIX  (NIMG * HWX)          // 200704 = 784 * 256

// Intermediate y, NHWC fp16: [img*hw][256]
__device__ __half g_y[(size_t)NPIX * CTOT];
// GEMM weights fp16: gA[oc 64][tap*64+ic], gB[oc 192][tap*192+ic]
__device__ __half g_wA[64 * 576];
__device__ __half g_wB[192 * 1728];

__device__ __forceinline__ uint32_t smem_u32(const void* p) {
    uint32_t a;
    asm("{ .reg .u64 t; cvta.to.shared.u64 t, %1; cvt.u32.u64 %0, t; }" : "=r"(a) : "l"(p));
    return a;
}

// ---------------------------------------------------------------------------
// Stage 1: temporal DW conv, NCHW fp32 -> NHWC fp16, smem transpose.
// ---------------------------------------------------------------------------
__global__ __launch_bounds__(256) void temporal_nhwc_kernel(
    const float* __restrict__ x,
    const float* __restrict__ w11, const float* __restrict__ w13,
    const float* __restrict__ w15, const float* __restrict__ w17,
    const float* __restrict__ w21, const float* __restrict__ w23,
    const float* __restrict__ w25, const float* __restrict__ w27)
{
    __shared__ float s[32][33];
    const int tx = threadIdx.x, ty = threadIdx.y;
    const int n = blockIdx.z, c0 = blockIdx.y * 32, hw0 = blockIdx.x * 32;

    float v[4][8], o[4][8];
#pragma unroll
    for (int j = 0; j < 4; j++) {
        int c = c0 + ty * 4 + j;
        const float* xb = x + ((size_t)(n * 8) * CTOT + c) * HWX + hw0 + tx;
#pragma unroll
        for (int t = 0; t < 8; t++) v[j][t] = xb[(size_t)t * CTOT * HWX];
    }
#pragma unroll
    for (int j = 0; j < 4; j++) {
        int c = c0 + ty * 4 + j;
        int k, cg; const float* wp;
        if      (c < 16)  { k = 1; wp = w11; cg = c;       }
        else if (c < 32)  { k = 3; wp = w13; cg = c - 16;  }
        else if (c < 48)  { k = 5; wp = w15; cg = c - 32;  }
        else if (c < 64)  { k = 7; wp = w17; cg = c - 48;  }
        else if (c < 112) { k = 1; wp = w21; cg = c - 64;  }
        else if (c < 160) { k = 3; wp = w23; cg = c - 112; }
        else if (c < 208) { k = 5; wp = w25; cg = c - 160; }
        else              { k = 7; wp = w27; cg = c - 208; }
        float wr[7];
#pragma unroll
        for (int q = 0; q < 7; q++) wr[q] = (q < k) ? __ldg(&wp[cg * k + q]) : 0.0f;
        int pad = (k - 1) >> 1;
#pragma unroll
        for (int t = 0; t < 8; t++) {
            float sum = 0.0f;
#pragma unroll
            for (int q = 0; q < 7; q++) {
                int tt = t + q - pad;
                if (q < k && tt >= 0 && tt < 8) sum += wr[q] * v[j][tt];
            }
            o[j][t] = sum;
        }
    }
#pragma unroll
    for (int t = 0; t < 8; t++) {
#pragma unroll
        for (int j = 0; j < 4; j++) s[tx][ty * 4 + j] = o[j][t];
        __syncthreads();
        __half* yb = g_y + ((size_t)(n * 8 + t) * HWX + hw0) * CTOT + c0;
#pragma unroll
        for (int j = 0; j < 4; j++)
            yb[(size_t)(ty * 4 + j) * CTOT + tx] = __float2half_rn(s[ty * 4 + j][tx]);
        __syncthreads();
    }
}

// ---------------------------------------------------------------------------
// Weight prep: [oc][ic][3][3] -> [oc][tap*icn + ic], fp16
// ---------------------------------------------------------------------------
__global__ void prep_w_kernel(const float* __restrict__ w2d1,
                              const float* __restrict__ w2d2)
{
    int i = blockIdx.x * 256 + threadIdx.x;     // < 368640
    if (i < 64 * 576) {
        int oc = i / 576, r = i % 576, tap = r / 64, ic = r % 64;
        g_wA[i] = __float2half_rn(w2d1[(oc * 64 + ic) * 9 + tap]);
    } else {
        int j = i - 64 * 576;
        if (j < 192 * 1728) {
            int oc = j / 1728, r = j % 1728, tap = r / 192, ic = r % 192;
            g_wB[j] = __float2half_rn(w2d2[(oc * 192 + ic) * 9 + tap]);
        }
    }
}

// ---------------------------------------------------------------------------
// Stage 2: implicit GEMM with mma.sync.m16n8k16 fp16 (fp32 accum).
// Grid (4 octiles, 784 pixel tiles). CTA: 64 oc x 256 px, 8 warps of 32x64.
// smem (halves, stride 40/row): A[2][64][40], B[2][256][40] = 51200 B total.
// ---------------------------------------------------------------------------
#define A_BUF_B 5120u               // 64*40*2
#define B_BUF_B 20480u              // 256*40*2
#define SMEM_BYTES (2 * (A_BUF_B + B_BUF_B))   // 51200

__global__ __launch_bounds__(256) void gemm_conv_kernel(float* __restrict__ out)
{
    extern __shared__ __half smh[];
    const uint32_t smb = smem_u32(smh);
    const int tid = threadIdx.x, wid = tid >> 5, lane = tid & 31;
    const int octile = blockIdx.x;
    const int n0 = blockIdx.y * 256;

    const bool isA = (octile == 0);
    const int icn    = isA ? 64 : 192;
    const int Ktot   = isA ? 576 : 1728;
    const int nicb   = icn >> 5;          // 2 or 6 (32-wide ic blocks)
    const int nch    = Ktot >> 5;         // 18 or 54
    const int icbase = isA ? 0 : 64;
    const __half* Wg = isA ? g_wA : (g_wB + (size_t)(octile - 1) * 64 * 1728);

    // Per-thread B staging coords: 4 rows, r = (tid>>2) + it*64
    const int q4 = tid & 3;
    int pn[4], phh[4], pww[4];
#pragma unroll
    for (int it = 0; it < 4; ++it) {
        int r = (tid >> 2) + it * 64;
        int nn = n0 + r;
        int hw = nn % HWX;
        pn[it] = nn; phh[it] = hw / WW; pww[it] = hw % WW;
    }

    auto stage = [&](int ch, int buf) {
        int tap = ch / nicb, icq = ch - tap * nicb;
        int dy = tap / 3 - 1, dx = tap - (tap / 3) * 3 - 1;
        // A: 64 oc rows x 32 k halves (64B/row -> 4x16B), 1 op/thread
        {
            int m = tid >> 2;
            const __half* src = Wg + (size_t)m * Ktot + tap * icn + icq * 32 + q4 * 8;
            uint32_t dst = smb + buf * A_BUF_B + m * 80 + q4 * 16;
            asm volatile("cp.async.cg.shared.global [%0], [%1], 16;"
                         :: "r"(dst), "l"(src));
        }
        // B: 256 px rows x 32 ic halves, 4 ops/thread
        {
            int ic0 = icbase + icq * 32;
            int shift = dy * WW + dx;
#pragma unroll
            for (int it = 0; it < 4; ++it) {
                int r = (tid >> 2) + it * 64;
                bool inb = ((unsigned)(phh[it] + dy) < 56u) &&
                           ((unsigned)(pww[it] + dx) < 56u);
                const __half* src = g_y + (size_t)(pn[it] + shift) * CTOT + ic0 + q4 * 8;
                if (!inb) src = g_y;
                uint32_t sz = inb ? 16u : 0u;
                uint32_t dst = smb + 2 * A_BUF_B + buf * B_BUF_B + r * 80 + q4 * 16;
                asm volatile("cp.async.cg.shared.global [%0], [%1], 16, %2;"
                             :: "r"(dst), "l"(src), "r"(sz));
            }
        }
        asm volatile("cp.async.commit_group;" ::: "memory");
    };

    float acc[2][8][4];
#pragma unroll
    for (int mt = 0; mt < 2; ++mt)
#pragma unroll
        for (int nt = 0; nt < 8; ++nt)
#pragma unroll
            for (int e = 0; e < 4; ++e) acc[mt][nt][e] = 0.0f;

    const int wm = wid & 1, wn = wid >> 1;
    const int g = lane >> 2, t = lane & 3;

    stage(0, 0);

    for (int ch = 0; ch < nch; ++ch) {
        if (ch + 1 < nch) {
            stage(ch + 1, (ch + 1) & 1);
            asm volatile("cp.async.wait_group 1;" ::: "memory");
        } else {
            asm volatile("cp.async.wait_group 0;" ::: "memory");
        }
        __syncthreads();

        // word-indexed (b32 = 2 halves) views; row stride = 20 words
        const uint32_t* sA32 = (const uint32_t*)smh + (ch & 1) * (A_BUF_B / 4);
        const uint32_t* sB32 = (const uint32_t*)smh + 2 * (A_BUF_B / 4)
                               + (ch & 1) * (B_BUF_B / 4);
        const uint32_t* aR = sA32 + (wm * 32 + g) * 20;
        const uint32_t* bR = sB32 + (wn * 64 + g) * 20;

#pragma unroll
        for (int ks = 0; ks < 2; ++ks) {       // two K=16 steps
            int w0 = ks * 8 + t;
            uint32_t a[2][4], b[8][2];
#pragma unroll
            for (int mt = 0; mt < 2; ++mt) {
                const uint32_t* p = aR + mt * 16 * 20;
                a[mt][0] = p[w0];
                a[mt][1] = p[8 * 20 + w0];
                a[mt][2] = p[w0 + 4];
                a[mt][3] = p[8 * 20 + w0 + 4];
            }
#pragma unroll
            for (int nt = 0; nt < 8; ++nt) {
                const uint32_t* p = bR + nt * 8 * 20;
                b[nt][0] = p[w0];
                b[nt][1] = p[w0 + 4];
            }
#pragma unroll
            for (int mt = 0; mt < 2; ++mt)
#pragma unroll
                for (int nt = 0; nt < 8; ++nt)
                    asm volatile(
                        "mma.sync.aligned.m16n8k16.row.col.f32.f16.f16.f32 "
                        "{%0,%1,%2,%3}, {%4,%5,%6,%7}, {%8,%9}, {%0,%1,%2,%3};"
                        : "+f"(acc[mt][nt][0]), "+f"(acc[mt][nt][1]),
                          "+f"(acc[mt][nt][2]), "+f"(acc[mt][nt][3])
                        : "r"(a[mt][0]), "r"(a[mt][1]), "r"(a[mt][2]), "r"(a[mt][3]),
                          "r"(b[nt][0]), "r"(b[nt][1]));
        }
        __syncthreads();
    }

    // Epilogue: D[oc][pixel] -> out NCHW fp32, float2 stores
    const int oc_b = octile * 64 + wm * 32 + g;
#pragma unroll
    for (int mt = 0; mt < 2; ++mt) {
#pragma unroll
        for (int nt = 0; nt < 8; ++nt) {
            int nn  = n0 + wn * 64 + nt * 8 + 2 * t;
            int img = nn / HWX, hw = nn - img * HWX;
            size_t r0 = ((size_t)img * CTOT + (oc_b + mt * 16))     * HWX + hw;
            size_t r1 = ((size_t)img * CTOT + (oc_b + mt * 16 + 8)) * HWX + hw;
            *(float2*)(out + r0) = make_float2(acc[mt][nt][0], acc[mt][nt][1]);
            *(float2*)(out + r1) = make_float2(acc[mt][nt][2], acc[mt][nt][3]);
        }
    }
}

// ---------------------------------------------------------------------------
// Inputs: x, w11, w13, w15, w17, w21, w23, w25, w27, w2d1, w2d2, n_segment
// ---------------------------------------------------------------------------
extern "C" void kernel_launch(void* const* d_in, const int* in_sizes, int n_in,
                              void* d_out, int out_size)
{
    const float* x    = (const float*)d_in[0];
    const float* w11  = (const float*)d_in[1];
    const float* w13  = (const float*)d_in[2];
    const float* w15  = (const float*)d_in[3];
    const float* w17  = (const float*)d_in[4];
    const float* w21  = (const float*)d_in[5];
    const float* w23  = (const float*)d_in[6];
    const float* w25  = (const float*)d_in[7];
    const float* w27  = (const float*)d_in[8];
    const float* w2d1 = (const float*)d_in[9];
    const float* w2d2 = (const float*)d_in[10];
    float* out = (float*)d_out;

    cudaFuncSetAttribute(gemm_conv_kernel,
                         cudaFuncAttributeMaxDynamicSharedMemorySize, SMEM_BYTES);

    dim3 g1(98, 8, 8), b1(32, 8);
    temporal_nhwc_kernel<<<g1, b1>>>(x, w11, w13, w15, w17, w21, w23, w25, w27);
    prep_w_kernel<<<1440, 256>>>(w2d1, w2d2);
    gemm_conv_kernel<<<dim3(4, 784), 256, SMEM_BYTES>>>(out);
}

// round 9
// speedup vs baseline: 9.7042x; 1.0290x over previous
#include <cuda_runtime.h>
#include <cuda_fp16.h>
#include <cstdint>

#define HWX   3136
#define WW    56
#define CTOT  256
#define NIMG  64
#define NPIX  (NIMG * HWX)          // 200704 = 784 * 256

// Intermediate y, NHWC fp16: [img*hw][256]
__device__ __half g_y[(size_t)NPIX * CTOT];
// GEMM weights fp16: gA[oc 64][tap*64+ic], gB[oc 192][tap*192+ic]
__device__ __half g_wA[64 * 576];
__device__ __half g_wB[192 * 1728];

__device__ __forceinline__ uint32_t smem_u32(const void* p) {
    uint32_t a;
    asm("{ .reg .u64 t; cvta.to.shared.u64 t, %1; cvt.u32.u64 %0, t; }" : "=r"(a) : "l"(p));
    return a;
}

// ---------------------------------------------------------------------------
// Stage 1: temporal DW conv, NCHW fp32 -> NHWC fp16, smem transpose.
// ---------------------------------------------------------------------------
__global__ __launch_bounds__(256) void temporal_nhwc_kernel(
    const float* __restrict__ x,
    const float* __restrict__ w11, const float* __restrict__ w13,
    const float* __restrict__ w15, const float* __restrict__ w17,
    const float* __restrict__ w21, const float* __restrict__ w23,
    const float* __restrict__ w25, const float* __restrict__ w27)
{
    __shared__ float s[32][33];
    const int tx = threadIdx.x, ty = threadIdx.y;
    const int n = blockIdx.z, c0 = blockIdx.y * 32, hw0 = blockIdx.x * 32;

    float v[4][8], o[4][8];
#pragma unroll
    for (int j = 0; j < 4; j++) {
        int c = c0 + ty * 4 + j;
        const float* xb = x + ((size_t)(n * 8) * CTOT + c) * HWX + hw0 + tx;
#pragma unroll
        for (int t = 0; t < 8; t++) v[j][t] = xb[(size_t)t * CTOT * HWX];
    }
#pragma unroll
    for (int j = 0; j < 4; j++) {
        int c = c0 + ty * 4 + j;
        int k, cg; const float* wp;
        if      (c < 16)  { k = 1; wp = w11; cg = c;       }
        else if (c < 32)  { k = 3; wp = w13; cg = c - 16;  }
        else if (c < 48)  { k = 5; wp = w15; cg = c - 32;  }
        else if (c < 64)  { k = 7; wp = w17; cg = c - 48;  }
        else if (c < 112) { k = 1; wp = w21; cg = c - 64;  }
        else if (c < 160) { k = 3; wp = w23; cg = c - 112; }
        else if (c < 208) { k = 5; wp = w25; cg = c - 160; }
        else              { k = 7; wp = w27; cg = c - 208; }
        float wr[7];
#pragma unroll
        for (int q = 0; q < 7; q++) wr[q] = (q < k) ? __ldg(&wp[cg * k + q]) : 0.0f;
        int pad = (k - 1) >> 1;
#pragma unroll
        for (int t = 0; t < 8; t++) {
            float sum = 0.0f;
#pragma unroll
            for (int q = 0; q < 7; q++) {
                int tt = t + q - pad;
                if (q < k && tt >= 0 && tt < 8) sum += wr[q] * v[j][tt];
            }
            o[j][t] = sum;
        }
    }
#pragma unroll
    for (int t = 0; t < 8; t++) {
#pragma unroll
        for (int j = 0; j < 4; j++) s[tx][ty * 4 + j] = o[j][t];
        __syncthreads();
        __half* yb = g_y + ((size_t)(n * 8 + t) * HWX + hw0) * CTOT + c0;
#pragma unroll
        for (int j = 0; j < 4; j++)
            yb[(size_t)(ty * 4 + j) * CTOT + tx] = __float2half_rn(s[ty * 4 + j][tx]);
        __syncthreads();
    }
}

// ---------------------------------------------------------------------------
// Weight prep: [oc][ic][3][3] -> [oc][tap*icn + ic], fp16
// ---------------------------------------------------------------------------
__global__ void prep_w_kernel(const float* __restrict__ w2d1,
                              const float* __restrict__ w2d2)
{
    int i = blockIdx.x * 256 + threadIdx.x;     // < 368640
    if (i < 64 * 576) {
        int oc = i / 576, r = i % 576, tap = r / 64, ic = r % 64;
        g_wA[i] = __float2half_rn(w2d1[(oc * 64 + ic) * 9 + tap]);
    } else {
        int j = i - 64 * 576;
        if (j < 192 * 1728) {
            int oc = j / 1728, r = j % 1728, tap = r / 192, ic = r % 192;
            g_wB[j] = __float2half_rn(w2d2[(oc * 192 + ic) * 9 + tap]);
        }
    }
}

// ---------------------------------------------------------------------------
// Stage 2: implicit GEMM, mma.sync.m16n8k16 fp16 (fp32 accum).
// Grid (4 octiles, 784 pixel tiles). CTA: 64 oc x 256 px, 8 warps of 32x64.
// 3-stage cp.async pipeline, ldmatrix.x4 fragment loads, 1 sync/chunk.
// smem halves, 40/row: per buffer A[64][40] + B[256][40] = 25600 B; x3.
// ---------------------------------------------------------------------------
#define A_BUF_B 5120u
#define B_BUF_B 20480u
#define BUF_STRIDE 25600u
#define SMEM_BYTES (3u * BUF_STRIDE)     // 76800

#define LDSM_X4(r0, r1, r2, r3, addr) \
    asm volatile("ldmatrix.sync.aligned.m8n8.x4.shared.b16 {%0,%1,%2,%3}, [%4];" \
        : "=r"(r0), "=r"(r1), "=r"(r2), "=r"(r3) : "r"(addr))

__global__ __launch_bounds__(256, 2) void gemm_conv_kernel(float* __restrict__ out)
{
    extern __shared__ __half smh[];
    const uint32_t smb = smem_u32(smh);
    const int tid = threadIdx.x, wid = tid >> 5, lane = tid & 31;
    const int octile = blockIdx.x;
    const int n0 = blockIdx.y * 256;

    const bool isA = (octile == 0);
    const int icn    = isA ? 64 : 192;
    const int Ktot   = isA ? 576 : 1728;
    const int nicb   = icn >> 5;          // 2 or 6
    const int nch    = Ktot >> 5;         // 18 or 54
    const int icbase = isA ? 0 : 64;
    const __half* Wg = isA ? g_wA : (g_wB + (size_t)(octile - 1) * 64 * 1728);

    const int q4 = tid & 3;
    int pn[4], phh[4], pww[4];
#pragma unroll
    for (int it = 0; it < 4; ++it) {
        int r = (tid >> 2) + it * 64;
        int nn = n0 + r;
        int hw = nn % HWX;
        pn[it] = nn; phh[it] = hw / WW; pww[it] = hw % WW;
    }

    auto stage = [&](int ch, int buf) {
        int tap = ch / nicb, icq = ch - tap * nicb;
        int dy = tap / 3 - 1, dx = tap - (tap / 3) * 3 - 1;
        {   // A: 64 oc rows x 32 k halves
            int m = tid >> 2;
            const __half* src = Wg + (size_t)m * Ktot + tap * icn + icq * 32 + q4 * 8;
            uint32_t dst = smb + buf * BUF_STRIDE + m * 80 + q4 * 16;
            asm volatile("cp.async.cg.shared.global [%0], [%1], 16;"
                         :: "r"(dst), "l"(src));
        }
        {   // B: 256 px rows x 32 ic halves
            int ic0 = icbase + icq * 32;
            int shift = dy * WW + dx;
#pragma unroll
            for (int it = 0; it < 4; ++it) {
                int r = (tid >> 2) + it * 64;
                bool inb = ((unsigned)(phh[it] + dy) < 56u) &&
                           ((unsigned)(pww[it] + dx) < 56u);
                const __half* src = g_y + (size_t)(pn[it] + shift) * CTOT + ic0 + q4 * 8;
                if (!inb) src = g_y;
                uint32_t sz = inb ? 16u : 0u;
                uint32_t dst = smb + buf * BUF_STRIDE + A_BUF_B + r * 80 + q4 * 16;
                asm volatile("cp.async.cg.shared.global [%0], [%1], 16, %2;"
                             :: "r"(dst), "l"(src), "r"(sz));
            }
        }
        asm volatile("cp.async.commit_group;" ::: "memory");
    };

    float acc[2][8][4];
#pragma unroll
    for (int mt = 0; mt < 2; ++mt)
#pragma unroll
        for (int nt = 0; nt < 8; ++nt)
#pragma unroll
            for (int e = 0; e < 4; ++e) acc[mt][nt][e] = 0.0f;

    const int wm = wid & 1, wn = wid >> 1;
    const int l15 = lane & 15;           // ldmatrix row-within-16
    const int khalf = (lane >> 4) * 16;  // byte offset: k 0-7 vs 8-15

    stage(0, 0);
    stage(1, 1);

    for (int ch = 0; ch < nch; ++ch) {
        if (ch + 1 < nch)
            asm volatile("cp.async.wait_group 1;" ::: "memory");
        else
            asm volatile("cp.async.wait_group 0;" ::: "memory");
        __syncthreads();                          // all warps done with ch-1
        if (ch + 2 < nch) stage(ch + 2, (ch + 2) % 3);

        const uint32_t bb = smb + (ch % 3) * BUF_STRIDE;
        // per-lane ldmatrix base addresses
        const uint32_t aA = bb + (wm * 32 + l15) * 80 + khalf;
        const uint32_t aB = bb + A_BUF_B + (wn * 64 + l15) * 80 + khalf;

#pragma unroll
        for (int ks = 0; ks < 2; ++ks) {
            uint32_t a[2][4], b[8][2];
#pragma unroll
            for (int mt = 0; mt < 2; ++mt)
                LDSM_X4(a[mt][0], a[mt][1], a[mt][2], a[mt][3],
                        aA + mt * (16 * 80) + ks * 32);
#pragma unroll
            for (int p = 0; p < 4; ++p)
                LDSM_X4(b[2 * p][0], b[2 * p + 1][0], b[2 * p][1], b[2 * p + 1][1],
                        aB + p * (16 * 80) + ks * 32);
#pragma unroll
            for (int mt = 0; mt < 2; ++mt)
#pragma unroll
                for (int nt = 0; nt < 8; ++nt)
                    asm volatile(
                        "mma.sync.aligned.m16n8k16.row.col.f32.f16.f16.f32 "
                        "{%0,%1,%2,%3}, {%4,%5,%6,%7}, {%8,%9}, {%0,%1,%2,%3};"
                        : "+f"(acc[mt][nt][0]), "+f"(acc[mt][nt][1]),
                          "+f"(acc[mt][nt][2]), "+f"(acc[mt][nt][3])
                        : "r"(a[mt][0]), "r"(a[mt][1]), "r"(a[mt][2]), "r"(a[mt][3]),
                          "r"(b[nt][0]), "r"(b[nt][1]));
        }
    }

    // Epilogue: D[oc][pixel] -> out NCHW fp32, float2 stores
    const int g = lane >> 2, t = lane & 3;
    const int oc_b = octile * 64 + wm * 32 + g;
#pragma unroll
    for (int mt = 0; mt < 2; ++mt) {
#pragma unroll
        for (int nt = 0; nt < 8; ++nt) {
            int nn  = n0 + wn * 64 + nt * 8 + 2 * t;
            int img = nn / HWX, hw = nn - img * HWX;
            size_t r0 = ((size_t)img * CTOT + (oc_b + mt * 16))     * HWX + hw;
            size_t r1 = ((size_t)img * CTOT + (oc_b + mt * 16 + 8)) * HWX + hw;
            *(float2*)(out + r0) = make_float2(acc[mt][nt][0], acc[mt][nt][1]);
            *(float2*)(out + r1) = make_float2(acc[mt][nt][2], acc[mt][nt][3]);
        }
    }
}

// ---------------------------------------------------------------------------
// Inputs: x, w11, w13, w15, w17, w21, w23, w25, w27, w2d1, w2d2, n_segment
// ---------------------------------------------------------------------------
extern "C" void kernel_launch(void* const* d_in, const int* in_sizes, int n_in,
                              void* d_out, int out_size)
{
    const float* x    = (const float*)d_in[0];
    const float* w11  = (const float*)d_in[1];
    const float* w13  = (const float*)d_in[2];
    const float* w15  = (const float*)d_in[3];
    const float* w17  = (const float*)d_in[4];
    const float* w21  = (const float*)d_in[5];
    const float* w23  = (const float*)d_in[6];
    const float* w25  = (const float*)d_in[7];
    const float* w27  = (const float*)d_in[8];
    const float* w2d1 = (const float*)d_in[9];
    const float* w2d2 = (const float*)d_in[10];
    float* out = (float*)d_out;

    cudaFuncSetAttribute(gemm_conv_kernel,
                         cudaFuncAttributeMaxDynamicSharedMemorySize, SMEM_BYTES);

    dim3 g1(98, 8, 8), b1(32, 8);
    temporal_nhwc_kernel<<<g1, b1>>>(x, w11, w13, w15, w17, w21, w23, w25, w27);
    prep_w_kernel<<<1440, 256>>>(w2d1, w2d2);
    gemm_conv_kernel<<<dim3(4, 784), 256, SMEM_BYTES>>>(out);
}

// round 10
// speedup vs baseline: 10.3680x; 1.0684x over previous
#include <cuda_runtime.h>
#include <cuda_fp16.h>
#include <cstdint>

#define HWX   3136
#define WW    56
#define CTOT  256
#define NIMG  64
#define NPIX  (NIMG * HWX)          // 200704
#define NTILE 50176                 // 64 img * 28*28 winograd tiles

// Intermediate y, NHWC fp32: [img*hw][256]
__device__ float g_y[(size_t)NPIX * CTOT];
// Winograd-transformed input V[pos 16][tile][ic 256], fp16
__device__ __half g_V[(size_t)16 * NTILE * 256];
// Winograd-transformed weights, fp16
__device__ __half g_UA[16 * 64 * 64];      // [p][oc][ic]
__device__ __half g_UB[16 * 192 * 192];    // [p][oc][ic]

__device__ __forceinline__ uint32_t smem_u32(const void* p) {
    uint32_t a;
    asm("{ .reg .u64 t; cvta.to.shared.u64 t, %1; cvt.u32.u64 %0, t; }" : "=r"(a) : "l"(p));
    return a;
}

// ---------------------------------------------------------------------------
// Stage 1: temporal DW conv, NCHW fp32 -> NHWC fp32, smem transpose.
// ---------------------------------------------------------------------------
__global__ __launch_bounds__(256) void temporal_nhwc_kernel(
    const float* __restrict__ x,
    const float* __restrict__ w11, const float* __restrict__ w13,
    const float* __restrict__ w15, const float* __restrict__ w17,
    const float* __restrict__ w21, const float* __restrict__ w23,
    const float* __restrict__ w25, const float* __restrict__ w27)
{
    __shared__ float s[32][33];
    const int tx = threadIdx.x, ty = threadIdx.y;
    const int n = blockIdx.z, c0 = blockIdx.y * 32, hw0 = blockIdx.x * 32;

    float v[4][8], o[4][8];
#pragma unroll
    for (int j = 0; j < 4; j++) {
        int c = c0 + ty * 4 + j;
        const float* xb = x + ((size_t)(n * 8) * CTOT + c) * HWX + hw0 + tx;
#pragma unroll
        for (int t = 0; t < 8; t++) v[j][t] = xb[(size_t)t * CTOT * HWX];
    }
#pragma unroll
    for (int j = 0; j < 4; j++) {
        int c = c0 + ty * 4 + j;
        int k, cg; const float* wp;
        if      (c < 16)  { k = 1; wp = w11; cg = c;       }
        else if (c < 32)  { k = 3; wp = w13; cg = c - 16;  }
        else if (c < 48)  { k = 5; wp = w15; cg = c - 32;  }
        else if (c < 64)  { k = 7; wp = w17; cg = c - 48;  }
        else if (c < 112) { k = 1; wp = w21; cg = c - 64;  }
        else if (c < 160) { k = 3; wp = w23; cg = c - 112; }
        else if (c < 208) { k = 5; wp = w25; cg = c - 160; }
        else              { k = 7; wp = w27; cg = c - 208; }
        float wr[7];
#pragma unroll
        for (int q = 0; q < 7; q++) wr[q] = (q < k) ? __ldg(&wp[cg * k + q]) : 0.0f;
        int pad = (k - 1) >> 1;
#pragma unroll
        for (int t = 0; t < 8; t++) {
            float sum = 0.0f;
#pragma unroll
            for (int q = 0; q < 7; q++) {
                int tt = t + q - pad;
                if (q < k && tt >= 0 && tt < 8) sum += wr[q] * v[j][tt];
            }
            o[j][t] = sum;
        }
    }
#pragma unroll
    for (int t = 0; t < 8; t++) {
#pragma unroll
        for (int j = 0; j < 4; j++) s[tx][ty * 4 + j] = o[j][t];
        __syncthreads();
        float* yb = g_y + ((size_t)(n * 8 + t) * HWX + hw0) * CTOT + c0;
#pragma unroll
        for (int j = 0; j < 4; j++)
            yb[(size_t)(ty * 4 + j) * CTOT + tx] = s[ty * 4 + j][tx];
        __syncthreads();
    }
}

// ---------------------------------------------------------------------------
// Winograd input transform: g_y (NHWC fp32) -> V[p][tile][ic] fp16.
// V = B^T d B; B^T = [[1,0,-1,0],[0,1,1,0],[0,-1,1,0],[0,1,0,-1]].
// CTA: 2 tiles x 128 ic-pairs. fp32 transform, single fp16 rounding.
// ---------------------------------------------------------------------------
__global__ __launch_bounds__(256) void wino_v_kernel()
{
    const int tid  = threadIdx.x;
    const int tile = blockIdx.x * 2 + (tid >> 7);
    const int icp  = tid & 127;
    const int img  = tile / 784, rem = tile % 784;
    const int tr = rem / 28, tc = rem % 28;
    const int h0 = 2 * tr - 1, w0 = 2 * tc - 1;
    const float* yb = g_y + (size_t)img * HWX * CTOT + icp * 2;

    float ex[4][4], ey[4][4];
#pragma unroll
    for (int c = 0; c < 4; ++c) {
        float dx[4], dy[4];
#pragma unroll
        for (int r = 0; r < 4; ++r) {
            int h = h0 + r, w = w0 + c;
            float2 v = make_float2(0.0f, 0.0f);
            if ((unsigned)h < 56u && (unsigned)w < 56u)
                v = *(const float2*)(yb + (size_t)(h * WW + w) * CTOT);
            dx[r] = v.x; dy[r] = v.y;
        }
        ex[0][c] = dx[0] - dx[2];  ey[0][c] = dy[0] - dy[2];
        ex[1][c] = dx[1] + dx[2];  ey[1][c] = dy[1] + dy[2];
        ex[2][c] = dx[2] - dx[1];  ey[2][c] = dy[2] - dy[1];
        ex[3][c] = dx[1] - dx[3];  ey[3][c] = dy[1] - dy[3];
    }
#pragma unroll
    for (int i = 0; i < 4; ++i) {
        float vx[4], vy[4];
        vx[0] = ex[i][0] - ex[i][2];  vy[0] = ey[i][0] - ey[i][2];
        vx[1] = ex[i][1] + ex[i][2];  vy[1] = ey[i][1] + ey[i][2];
        vx[2] = ex[i][2] - ex[i][1];  vy[2] = ey[i][2] - ey[i][1];
        vx[3] = ex[i][1] - ex[i][3];  vy[3] = ey[i][1] - ey[i][3];
#pragma unroll
        for (int j = 0; j < 4; ++j) {
            *(__half2*)(g_V + ((size_t)(i * 4 + j) * NTILE + tile) * 256 + icp * 2)
                = __floats2half2_rn(vx[j], vy[j]);
        }
    }
}

// ---------------------------------------------------------------------------
// Winograd weight transform: U = G g G^T, fp32 math, fp16 store.
// G = [[1,0,0],[.5,.5,.5],[.5,-.5,.5],[0,0,1]].
// ---------------------------------------------------------------------------
__global__ void wino_u_kernel(const float* __restrict__ w2d1,
                              const float* __restrict__ w2d2)
{
    int i = blockIdx.x * 256 + threadIdx.x;
    if (i >= 4096 + 36864) return;
    const float* src;
    __half* dst0; int rstride, rowoff;
    if (i < 4096) {
        int oc = i >> 6, ic = i & 63;
        src = w2d1 + (oc * 64 + ic) * 9;
        dst0 = g_UA; rstride = 64 * 64; rowoff = oc * 64 + ic;
    } else {
        int j = i - 4096;
        int oc = j / 192, ic = j % 192;
        src = w2d2 + (oc * 192 + ic) * 9;
        dst0 = g_UB; rstride = 192 * 192; rowoff = oc * 192 + ic;
    }
    float g[3][3];
#pragma unroll
    for (int a = 0; a < 3; ++a)
#pragma unroll
        for (int b = 0; b < 3; ++b) g[a][b] = src[a * 3 + b];
    float u[4][3];
#pragma unroll
    for (int b = 0; b < 3; ++b) {
        u[0][b] = g[0][b];
        u[1][b] = 0.5f * (g[0][b] + g[1][b] + g[2][b]);
        u[2][b] = 0.5f * (g[0][b] - g[1][b] + g[2][b]);
        u[3][b] = g[2][b];
    }
#pragma unroll
    for (int r = 0; r < 4; ++r) {
        float U0 = u[r][0];
        float U1 = 0.5f * (u[r][0] + u[r][1] + u[r][2]);
        float U2 = 0.5f * (u[r][0] - u[r][1] + u[r][2]);
        float U3 = u[r][2];
        dst0[(r * 4 + 0) * rstride + rowoff] = __float2half_rn(U0);
        dst0[(r * 4 + 1) * rstride + rowoff] = __float2half_rn(U1);
        dst0[(r * 4 + 2) * rstride + rowoff] = __float2half_rn(U2);
        dst0[(r * 4 + 3) * rstride + rowoff] = __float2half_rn(U3);
    }
}

// ---------------------------------------------------------------------------
// Winograd GEMM: per position p, M[p] = U[p] (64 oc x K) * V[p]^T (K x 64 tiles),
// K = 64 per iteration (2 sub-tiles of 32). Z += At-coef(p) * M after each p.
// CTA: 64 oc x 64 tiles, 8 warps (wm: 4 x 16 oc, wn: 2 x 32 tiles).
// 3-buffer cp.async pipeline, ldmatrix fragments (layout validated in R9).
// ---------------------------------------------------------------------------
#define BS 20480u      // per buffer: A[2][64][40] + B[2][64][40] halves
#define SMEM_BYTES (3u * BS)   // 61440

#define LDSM_X4(r0, r1, r2, r3, addr) \
    asm volatile("ldmatrix.sync.aligned.m8n8.x4.shared.b16 {%0,%1,%2,%3}, [%4];" \
        : "=r"(r0), "=r"(r1), "=r"(r2), "=r"(r3) : "r"(addr))

__global__ __launch_bounds__(256, 2) void wino_gemm_kernel(float* __restrict__ out)
{
    extern __shared__ __half smh[];
    const uint32_t smb = smem_u32(smh);
    const int tid = threadIdx.x, wid = tid >> 5, lane = tid & 31;
    const int octile = blockIdx.x;         // 0 = A-group, 1..3 = B-group
    const int n0 = blockIdx.y * 64;        // tile base

    const bool isA = (octile == 0);
    const int nkb  = isA ? 1 : 3;          // K=64 iterations per position
    const int nits = 16 * nkb;
    const int icb  = isA ? 0 : 64;
    const int ob64 = (octile - 1) * 64;

    const int m_ = tid >> 2, q4 = tid & 3;

    // staging cursor
    int sp = 0, sk = 0;
    auto stage = [&](int buf) {
#pragma unroll
        for (int kb = 0; kb < 2; ++kb) {
            const __half* asrc = isA
                ? g_UA + (sp * 64 + m_) * 64 + kb * 32 + q4 * 8
                : g_UB + ((size_t)(sp * 192 + ob64 + m_)) * 192 + sk * 64 + kb * 32 + q4 * 8;
            uint32_t da = smb + buf * BS + kb * 5120u + m_ * 80 + q4 * 16;
            asm volatile("cp.async.cg.shared.global [%0], [%1], 16;"
                         :: "r"(da), "l"(asrc));
            const __half* bsrc = g_V + ((size_t)sp * NTILE + n0 + m_) * 256
                                 + icb + sk * 64 + kb * 32 + q4 * 8;
            uint32_t db = smb + buf * BS + 10240u + kb * 5120u + m_ * 80 + q4 * 16;
            asm volatile("cp.async.cg.shared.global [%0], [%1], 16;"
                         :: "r"(db), "l"(bsrc));
        }
        asm volatile("cp.async.commit_group;" ::: "memory");
        if (++sk == nkb) { sk = 0; ++sp; }
    };

    float M[4][4];
    float Z[4][4][4];      // [nt][e][py*2+px]
#pragma unroll
    for (int a = 0; a < 4; ++a)
#pragma unroll
        for (int b = 0; b < 4; ++b)
#pragma unroll
            for (int c = 0; c < 4; ++c) Z[a][b][c] = 0.0f;

    const int wm = wid & 3, wn = wid >> 2;
    const int l15 = lane & 15;
    const int khalf = (lane >> 4) * 16;

    stage(0);
    stage(1);

    int p = 0, kcc = 0;
    for (int it = 0; it < nits; ++it) {
        if (it + 1 < nits)
            asm volatile("cp.async.wait_group 1;" ::: "memory");
        else
            asm volatile("cp.async.wait_group 0;" ::: "memory");
        __syncthreads();
        if (it + 2 < nits) stage((it + 2) % 3);

        if (kcc == 0) {
#pragma unroll
            for (int a = 0; a < 4; ++a)
#pragma unroll
                for (int b = 0; b < 4; ++b) M[a][b] = 0.0f;
        }

        const uint32_t bb = smb + (it % 3) * BS;
#pragma unroll
        for (int kb = 0; kb < 2; ++kb) {
            const uint32_t aA = bb + kb * 5120u + (wm * 16 + l15) * 80 + khalf;
            const uint32_t aB = bb + 10240u + kb * 5120u + (wn * 32 + l15) * 80 + khalf;
#pragma unroll
            for (int ks = 0; ks < 2; ++ks) {
                uint32_t a[4], b[4][2];
                LDSM_X4(a[0], a[1], a[2], a[3], aA + ks * 32);
                LDSM_X4(b[0][0], b[1][0], b[0][1], b[1][1], aB + ks * 32);
                LDSM_X4(b[2][0], b[3][0], b[2][1], b[3][1], aB + 16 * 80 + ks * 32);
#pragma unroll
                for (int nt = 0; nt < 4; ++nt)
                    asm volatile(
                        "mma.sync.aligned.m16n8k16.row.col.f32.f16.f16.f32 "
                        "{%0,%1,%2,%3}, {%4,%5,%6,%7}, {%8,%9}, {%0,%1,%2,%3};"
                        : "+f"(M[nt][0]), "+f"(M[nt][1]),
                          "+f"(M[nt][2]), "+f"(M[nt][3])
                        : "r"(a[0]), "r"(a[1]), "r"(a[2]), "r"(a[3]),
                          "r"(b[nt][0]), "r"(b[nt][1]));
            }
        }

        if (kcc == nkb - 1) {
            // inverse-transform fold: At = [[1,1,1,0],[0,1,-1,-1]]
            int pi = p >> 2, pj = p & 3;
            float fi0 = (pi < 3) ? 1.0f : 0.0f;
            float fi1 = (pi == 0) ? 0.0f : ((pi == 1) ? 1.0f : -1.0f);
            float fj0 = (pj < 3) ? 1.0f : 0.0f;
            float fj1 = (pj == 0) ? 0.0f : ((pj == 1) ? 1.0f : -1.0f);
            float c00 = fi0 * fj0, c01 = fi0 * fj1, c10 = fi1 * fj0, c11 = fi1 * fj1;
#pragma unroll
            for (int nt = 0; nt < 4; ++nt)
#pragma unroll
                for (int e = 0; e < 4; ++e) {
                    float m = M[nt][e];
                    Z[nt][e][0] += c00 * m;
                    Z[nt][e][1] += c01 * m;
                    Z[nt][e][2] += c10 * m;
                    Z[nt][e][3] += c11 * m;
                }
        }
        if (++kcc == nkb) { kcc = 0; ++p; }
    }

    // Epilogue: Z -> out NCHW fp32. Thread owns (oc g/g+8) x (tiles 2t, 2t+1).
    const int g = lane >> 2, t4 = lane & 3;
    const int oc0 = octile * 64 + wm * 16 + g;
#pragma unroll
    for (int nt = 0; nt < 4; ++nt) {
        int tl0 = n0 + wn * 32 + nt * 8 + 2 * t4;
#pragma unroll
        for (int et = 0; et < 2; ++et) {
            int tile = tl0 + et;
            int img = tile / 784, rem = tile % 784;
            int tr = rem / 28, tc = rem % 28;
            size_t obase = ((size_t)img * CTOT + oc0) * HWX + (2 * tr) * WW + 2 * tc;
#pragma unroll
            for (int er = 0; er < 2; ++er) {
                int e = er * 2 + et;
                size_t ob = obase + (size_t)er * 8 * HWX;
                *(float2*)(out + ob)      = make_float2(Z[nt][e][0], Z[nt][e][1]);
                *(float2*)(out + ob + WW) = make_float2(Z[nt][e][2], Z[nt][e][3]);
            }
        }
    }
}

// ---------------------------------------------------------------------------
// Inputs: x, w11, w13, w15, w17, w21, w23, w25, w27, w2d1, w2d2, n_segment
// ---------------------------------------------------------------------------
extern "C" void kernel_launch(void* const* d_in, const int* in_sizes, int n_in,
                              void* d_out, int out_size)
{
    const float* x    = (const float*)d_in[0];
    const float* w11  = (const float*)d_in[1];
    const float* w13  = (const float*)d_in[2];
    const float* w15  = (const float*)d_in[3];
    const float* w17  = (const float*)d_in[4];
    const float* w21  = (const float*)d_in[5];
    const float* w23  = (const float*)d_in[6];
    const float* w25  = (const float*)d_in[7];
    const float* w27  = (const float*)d_in[8];
    const float* w2d1 = (const float*)d_in[9];
    const float* w2d2 = (const float*)d_in[10];
    float* out = (float*)d_out;

    cudaFuncSetAttribute(wino_gemm_kernel,
                         cudaFuncAttributeMaxDynamicSharedMemorySize, SMEM_BYTES);

    dim3 g1(98, 8, 8), b1(32, 8);
    temporal_nhwc_kernel<<<g1, b1>>>(x, w11, w13, w15, w17, w21, w23, w25, w27);
    wino_u_kernel<<<160, 256>>>(w2d1, w2d2);
    wino_v_kernel<<<NTILE / 2, 256>>>();
    wino_gemm_kernel<<<dim3(4, 784), 256, SMEM_BYTES>>>(out);
}

// round 11
// speedup vs baseline: 10.3815x; 1.0013x over previous
#include <cuda_runtime.h>
#include <cuda_fp16.h>
#include <cstdint>

#define HWX   3136
#define WW    56
#define CTOT  256
#define NIMG  64
#define NPIX  (NIMG * HWX)          // 200704
#define NTILE 50176                 // 64 img * 28*28 winograd tiles

// Intermediate y, NHWC fp32: [img*hw][256]
__device__ float g_y[(size_t)NPIX * CTOT];
// Winograd-transformed input V[pos 16][tile][ic 256], fp16
__device__ __half g_V[(size_t)16 * NTILE * 256];
// Winograd-transformed weights, fp16
__device__ __half g_UA[16 * 64 * 64];      // [p][oc][ic]
__device__ __half g_UB[16 * 192 * 192];    // [p][oc][ic]

__device__ __forceinline__ uint32_t smem_u32(const void* p) {
    uint32_t a;
    asm("{ .reg .u64 t; cvta.to.shared.u64 t, %1; cvt.u32.u64 %0, t; }" : "=r"(a) : "l"(p));
    return a;
}

// ---------------------------------------------------------------------------
// Stage 1: temporal DW conv, NCHW fp32 -> NHWC fp32, smem transpose.
// ---------------------------------------------------------------------------
__global__ __launch_bounds__(256) void temporal_nhwc_kernel(
    const float* __restrict__ x,
    const float* __restrict__ w11, const float* __restrict__ w13,
    const float* __restrict__ w15, const float* __restrict__ w17,
    const float* __restrict__ w21, const float* __restrict__ w23,
    const float* __restrict__ w25, const float* __restrict__ w27)
{
    __shared__ float s[32][33];
    const int tx = threadIdx.x, ty = threadIdx.y;
    const int n = blockIdx.z, c0 = blockIdx.y * 32, hw0 = blockIdx.x * 32;

    float v[4][8], o[4][8];
#pragma unroll
    for (int j = 0; j < 4; j++) {
        int c = c0 + ty * 4 + j;
        const float* xb = x + ((size_t)(n * 8) * CTOT + c) * HWX + hw0 + tx;
#pragma unroll
        for (int t = 0; t < 8; t++) v[j][t] = xb[(size_t)t * CTOT * HWX];
    }
#pragma unroll
    for (int j = 0; j < 4; j++) {
        int c = c0 + ty * 4 + j;
        int k, cg; const float* wp;
        if      (c < 16)  { k = 1; wp = w11; cg = c;       }
        else if (c < 32)  { k = 3; wp = w13; cg = c - 16;  }
        else if (c < 48)  { k = 5; wp = w15; cg = c - 32;  }
        else if (c < 64)  { k = 7; wp = w17; cg = c - 48;  }
        else if (c < 112) { k = 1; wp = w21; cg = c - 64;  }
        else if (c < 160) { k = 3; wp = w23; cg = c - 112; }
        else if (c < 208) { k = 5; wp = w25; cg = c - 160; }
        else              { k = 7; wp = w27; cg = c - 208; }
        float wr[7];
#pragma unroll
        for (int q = 0; q < 7; q++) wr[q] = (q < k) ? __ldg(&wp[cg * k + q]) : 0.0f;
        int pad = (k - 1) >> 1;
#pragma unroll
        for (int t = 0; t < 8; t++) {
            float sum = 0.0f;
#pragma unroll
            for (int q = 0; q < 7; q++) {
                int tt = t + q - pad;
                if (q < k && tt >= 0 && tt < 8) sum += wr[q] * v[j][tt];
            }
            o[j][t] = sum;
        }
    }
#pragma unroll
    for (int t = 0; t < 8; t++) {
#pragma unroll
        for (int j = 0; j < 4; j++) s[tx][ty * 4 + j] = o[j][t];
        __syncthreads();
        float* yb = g_y + ((size_t)(n * 8 + t) * HWX + hw0) * CTOT + c0;
#pragma unroll
        for (int j = 0; j < 4; j++)
            yb[(size_t)(ty * 4 + j) * CTOT + tx] = s[ty * 4 + j][tx];
        __syncthreads();
    }
}

// ---------------------------------------------------------------------------
// Winograd input transform: g_y (NHWC fp32) -> V[p][tile][ic] fp16.
// ---------------------------------------------------------------------------
__global__ __launch_bounds__(256) void wino_v_kernel()
{
    const int tid  = threadIdx.x;
    const int tile = blockIdx.x * 2 + (tid >> 7);
    const int icp  = tid & 127;
    const int img  = tile / 784, rem = tile % 784;
    const int tr = rem / 28, tc = rem % 28;
    const int h0 = 2 * tr - 1, w0 = 2 * tc - 1;
    const float* yb = g_y + (size_t)img * HWX * CTOT + icp * 2;

    float ex[4][4], ey[4][4];
#pragma unroll
    for (int c = 0; c < 4; ++c) {
        float dx[4], dy[4];
#pragma unroll
        for (int r = 0; r < 4; ++r) {
            int h = h0 + r, w = w0 + c;
            float2 v = make_float2(0.0f, 0.0f);
            if ((unsigned)h < 56u && (unsigned)w < 56u)
                v = *(const float2*)(yb + (size_t)(h * WW + w) * CTOT);
            dx[r] = v.x; dy[r] = v.y;
        }
        ex[0][c] = dx[0] - dx[2];  ey[0][c] = dy[0] - dy[2];
        ex[1][c] = dx[1] + dx[2];  ey[1][c] = dy[1] + dy[2];
        ex[2][c] = dx[2] - dx[1];  ey[2][c] = dy[2] - dy[1];
        ex[3][c] = dx[1] - dx[3];  ey[3][c] = dy[1] - dy[3];
    }
#pragma unroll
    for (int i = 0; i < 4; ++i) {
        float vx[4], vy[4];
        vx[0] = ex[i][0] - ex[i][2];  vy[0] = ey[i][0] - ey[i][2];
        vx[1] = ex[i][1] + ex[i][2];  vy[1] = ey[i][1] + ey[i][2];
        vx[2] = ex[i][2] - ex[i][1];  vy[2] = ey[i][2] - ey[i][1];
        vx[3] = ex[i][1] - ex[i][3];  vy[3] = ey[i][1] - ey[i][3];
#pragma unroll
        for (int j = 0; j < 4; ++j) {
            *(__half2*)(g_V + ((size_t)(i * 4 + j) * NTILE + tile) * 256 + icp * 2)
                = __floats2half2_rn(vx[j], vy[j]);
        }
    }
}

// ---------------------------------------------------------------------------
// Winograd weight transform: U = G g G^T.
// ---------------------------------------------------------------------------
__global__ void wino_u_kernel(const float* __restrict__ w2d1,
                              const float* __restrict__ w2d2)
{
    int i = blockIdx.x * 256 + threadIdx.x;
    if (i >= 4096 + 36864) return;
    const float* src;
    __half* dst0; int rstride, rowoff;
    if (i < 4096) {
        int oc = i >> 6, ic = i & 63;
        src = w2d1 + (oc * 64 + ic) * 9;
        dst0 = g_UA; rstride = 64 * 64; rowoff = oc * 64 + ic;
    } else {
        int j = i - 4096;
        int oc = j / 192, ic = j % 192;
        src = w2d2 + (oc * 192 + ic) * 9;
        dst0 = g_UB; rstride = 192 * 192; rowoff = oc * 192 + ic;
    }
    float g[3][3];
#pragma unroll
    for (int a = 0; a < 3; ++a)
#pragma unroll
        for (int b = 0; b < 3; ++b) g[a][b] = src[a * 3 + b];
    float u[4][3];
#pragma unroll
    for (int b = 0; b < 3; ++b) {
        u[0][b] = g[0][b];
        u[1][b] = 0.5f * (g[0][b] + g[1][b] + g[2][b]);
        u[2][b] = 0.5f * (g[0][b] - g[1][b] + g[2][b]);
        u[3][b] = g[2][b];
    }
#pragma unroll
    for (int r = 0; r < 4; ++r) {
        float U0 = u[r][0];
        float U1 = 0.5f * (u[r][0] + u[r][1] + u[r][2]);
        float U2 = 0.5f * (u[r][0] - u[r][1] + u[r][2]);
        float U3 = u[r][2];
        dst0[(r * 4 + 0) * rstride + rowoff] = __float2half_rn(U0);
        dst0[(r * 4 + 1) * rstride + rowoff] = __float2half_rn(U1);
        dst0[(r * 4 + 2) * rstride + rowoff] = __float2half_rn(U2);
        dst0[(r * 4 + 3) * rstride + rowoff] = __float2half_rn(U3);
    }
}

// ---------------------------------------------------------------------------
// Winograd GEMM v2: position-level pipeline.
// Per position p: one buffer holds A[64 oc][icn] + B[64 tiles][icn] halves
// (contiguous K, row stride icn*2+16 bytes). One commit / one wait / one
// __syncthreads / one Z-fold per position. Double-buffered across positions.
// CTA: 64 oc x 64 tiles, 8 warps (4 x 16 oc, 2 x 32 tiles).
// ---------------------------------------------------------------------------
#define SMEM_BYTES 102400u       // 2 buffers x (128 rows x 400 B) at icn=192

#define LDSM_X4(r0, r1, r2, r3, addr) \
    asm volatile("ldmatrix.sync.aligned.m8n8.x4.shared.b16 {%0,%1,%2,%3}, [%4];" \
        : "=r"(r0), "=r"(r1), "=r"(r2), "=r"(r3) : "r"(addr))

__global__ __launch_bounds__(256, 2) void wino_gemm_kernel(float* __restrict__ out)
{
    extern __shared__ __half smh[];
    const uint32_t smb = smem_u32(smh);
    const int tid = threadIdx.x, wid = tid >> 5, lane = tid & 31;
    const int octile = blockIdx.x;         // 0 = A-group, 1..3 = B-group
    const int n0 = blockIdx.y * 64;        // tile base

    const bool isA = (octile == 0);
    const int icn  = isA ? 64 : 192;
    const int icb  = isA ? 0 : 64;
    const int ob64 = (octile - 1) * 64;
    const uint32_t st    = icn * 2 + 16;   // 144 or 400 bytes/row
    const uint32_t boff  = 64u * st;       // B region offset in buffer
    const uint32_t bufsz = 128u * st;      // A + B regions
    const int chunks = icn >> 3;           // 16B chunks per row: 8 or 24
    const int tot    = 64 * chunks;        // per-operand chunk count

    const __half* Abase = isA ? g_UA : (g_UB + (size_t)ob64 * 192);
    const size_t  Apstride = (size_t)icn * (isA ? 64 : 192);   // per-position A stride
    const __half* Bbase = g_V + (size_t)n0 * 256 + icb;

    auto stage = [&](int p, int buf) {
        const __half* As = Abase + (size_t)p * Apstride;
        const uint32_t bb = smb + buf * bufsz;
        for (int i = tid; i < tot; i += 256) {
            int row = i / chunks, kq = i - row * chunks;
            const __half* src = As + (size_t)row * icn + kq * 8;
            uint32_t dst = bb + row * st + kq * 16;
            asm volatile("cp.async.cg.shared.global [%0], [%1], 16;"
                         :: "r"(dst), "l"(src));
        }
        const __half* Bs = Bbase + (size_t)p * NTILE * 256;
        for (int i = tid; i < tot; i += 256) {
            int row = i / chunks, kq = i - row * chunks;
            const __half* src = Bs + (size_t)row * 256 + kq * 8;
            uint32_t dst = bb + boff + row * st + kq * 16;
            asm volatile("cp.async.cg.shared.global [%0], [%1], 16;"
                         :: "r"(dst), "l"(src));
        }
        asm volatile("cp.async.commit_group;" ::: "memory");
    };

    float Z[4][4][4];      // [nt][e][2x2 out pixel]
#pragma unroll
    for (int a = 0; a < 4; ++a)
#pragma unroll
        for (int b = 0; b < 4; ++b)
#pragma unroll
            for (int c = 0; c < 4; ++c) Z[a][b][c] = 0.0f;

    const int wm = wid & 3, wn = wid >> 2;
    const int l15 = lane & 15;
    const int kh16 = (lane >> 4) * 16;

    stage(0, 0);

    for (int p = 0; p < 16; ++p) {
        if (p < 15) {
            stage(p + 1, (p + 1) & 1);
            asm volatile("cp.async.wait_group 1;" ::: "memory");
        } else {
            asm volatile("cp.async.wait_group 0;" ::: "memory");
        }
        __syncthreads();   // buffer p&1 fully landed; all warps past p-1

        float M[4][4];
#pragma unroll
        for (int a = 0; a < 4; ++a)
#pragma unroll
            for (int b = 0; b < 4; ++b) M[a][b] = 0.0f;

        const uint32_t bb = smb + (p & 1) * bufsz;
        const uint32_t aA = bb + (wm * 16 + l15) * st + kh16;
        const uint32_t aB = bb + boff + (wn * 32 + l15) * st + kh16;

        const int nks = icn >> 4;
#pragma unroll 4
        for (int ks = 0; ks < nks; ++ks) {
            uint32_t a[4], b[4][2];
            LDSM_X4(a[0], a[1], a[2], a[3], aA + ks * 32);
            LDSM_X4(b[0][0], b[1][0], b[0][1], b[1][1], aB + ks * 32);
            LDSM_X4(b[2][0], b[3][0], b[2][1], b[3][1], aB + 16 * st + ks * 32);
#pragma unroll
            for (int nt = 0; nt < 4; ++nt)
                asm volatile(
                    "mma.sync.aligned.m16n8k16.row.col.f32.f16.f16.f32 "
                    "{%0,%1,%2,%3}, {%4,%5,%6,%7}, {%8,%9}, {%0,%1,%2,%3};"
                    : "+f"(M[nt][0]), "+f"(M[nt][1]),
                      "+f"(M[nt][2]), "+f"(M[nt][3])
                    : "r"(a[0]), "r"(a[1]), "r"(a[2]), "r"(a[3]),
                      "r"(b[nt][0]), "r"(b[nt][1]));
        }
        __syncthreads();   // all warps done reading buffer p&1

        // inverse-transform fold: At = [[1,1,1,0],[0,1,-1,-1]]
        int pi = p >> 2, pj = p & 3;
        float fi0 = (pi < 3) ? 1.0f : 0.0f;
        float fi1 = (pi == 0) ? 0.0f : ((pi == 1) ? 1.0f : -1.0f);
        float fj0 = (pj < 3) ? 1.0f : 0.0f;
        float fj1 = (pj == 0) ? 0.0f : ((pj == 1) ? 1.0f : -1.0f);
        float c00 = fi0 * fj0, c01 = fi0 * fj1, c10 = fi1 * fj0, c11 = fi1 * fj1;
#pragma unroll
        for (int nt = 0; nt < 4; ++nt)
#pragma unroll
            for (int e = 0; e < 4; ++e) {
                float m = M[nt][e];
                Z[nt][e][0] += c00 * m;
                Z[nt][e][1] += c01 * m;
                Z[nt][e][2] += c10 * m;
                Z[nt][e][3] += c11 * m;
            }
    }

    // Epilogue: Z -> out NCHW fp32.
    const int g = lane >> 2, t4 = lane & 3;
    const int oc0 = octile * 64 + wm * 16 + g;
#pragma unroll
    for (int nt = 0; nt < 4; ++nt) {
        int tl0 = n0 + wn * 32 + nt * 8 + 2 * t4;
#pragma unroll
        for (int et = 0; et < 2; ++et) {
            int tile = tl0 + et;
            int img = tile / 784, rem = tile % 784;
            int tr = rem / 28, tc = rem % 28;
            size_t obase = ((size_t)img * CTOT + oc0) * HWX + (2 * tr) * WW + 2 * tc;
#pragma unroll
            for (int er = 0; er < 2; ++er) {
                int e = er * 2 + et;
                size_t ob = obase + (size_t)er * 8 * HWX;
                *(float2*)(out + ob)      = make_float2(Z[nt][e][0], Z[nt][e][1]);
                *(float2*)(out + ob + WW) = make_float2(Z[nt][e][2], Z[nt][e][3]);
            }
        }
    }
}

// ---------------------------------------------------------------------------
// Inputs: x, w11, w13, w15, w17, w21, w23, w25, w27, w2d1, w2d2, n_segment
// ---------------------------------------------------------------------------
extern "C" void kernel_launch(void* const* d_in, const int* in_sizes, int n_in,
                              void* d_out, int out_size)
{
    const float* x    = (const float*)d_in[0];
    const float* w11  = (const float*)d_in[1];
    const float* w13  = (const float*)d_in[2];
    const float* w15  = (const float*)d_in[3];
    const float* w17  = (const float*)d_in[4];
    const float* w21  = (const float*)d_in[5];
    const float* w23  = (const float*)d_in[6];
    const float* w25  = (const float*)d_in[7];
    const float* w27  = (const float*)d_in[8];
    const float* w2d1 = (const float*)d_in[9];
    const float* w2d2 = (const float*)d_in[10];
    float* out = (float*)d_out;

    cudaFuncSetAttribute(wino_gemm_kernel,
                         cudaFuncAttributeMaxDynamicSharedMemorySize, SMEM_BYTES);

    dim3 g1(98, 8, 8), b1(32, 8);
    temporal_nhwc_kernel<<<g1, b1>>>(x, w11, w13, w15, w17, w21, w23, w25, w27);
    wino_u_kernel<<<160, 256>>>(w2d1, w2d2);
    wino_v_kernel<<<NTILE / 2, 256>>>();
    wino_gemm_kernel<<<dim3(4, 784), 256, SMEM_BYTES>>>(out);
}